// round 2
// baseline (speedup 1.0000x reference)
#include <cuda_runtime.h>
#include <math.h>

#define NN   50000
#define EE   1600000
#define ET   (EE + NN)     // edges incl. self loops = 1,650,000
#define INC  256
#define HC   128           // H*C
#define HH   4
#define CC   32
#define OUTC 64

// ---------------- scratch (device globals; no allocation allowed) -------------
__device__ __align__(16) float g_h[(size_t)NN * HC];        // 25.6 MB
__device__ __align__(16) float g_asrc[(size_t)NN * HH];
__device__ __align__(16) float g_adst[(size_t)NN * HH];
__device__ __align__(16) float g_emax[(size_t)NN * HH];
__device__ __align__(16) float g_den[(size_t)NN * HH];
__device__ __align__(16) float g_ex[(size_t)ET * HH];       // 26.4 MB
__device__ __align__(16) float g_agg[(size_t)NN * HC];      // 25.6 MB
__device__ __align__(16) int2  g_edge[(size_t)ET];          // 13.2 MB

// ---------------- helpers ----------------------------------------------------
__device__ __forceinline__ void atomicMaxF(float* addr, float v) {
    // valid for any sign mix when initialized to -inf
    if (v >= 0.0f) atomicMax((int*)addr, __float_as_int(v));
    else           atomicMin((unsigned int*)addr, __float_as_uint(v));
}

__device__ __forceinline__ float leaky(float v) {
    return v >= 0.0f ? v : 0.2f * v;
}

// ---------------- K1: h = x @ W  (64x128 tile per block) ---------------------
__global__ void k_gemm1(const float* __restrict__ x, const float* __restrict__ W) {
    __shared__ float xs[64][64];     // 16 KB
    __shared__ float ws[64][128];    // 32 KB
    const int t  = threadIdx.x;
    const int tx = t & 31;           // column group: cols tx*4 .. tx*4+3
    const int ty = t >> 5;           // row group:   rows ty, ty+8, ..., ty+56
    const int row0 = blockIdx.x * 64;

    float4 acc[8];
#pragma unroll
    for (int i = 0; i < 8; i++) acc[i] = make_float4(0.f, 0.f, 0.f, 0.f);

    for (int kt = 0; kt < 4; kt++) {
        // load x tile: 64 rows x 64 k  (1024 float4)
#pragma unroll
        for (int i = 0; i < 4; i++) {
            int id = t + i * 256;
            int r  = id >> 4;        // 16 float4 per row
            int c4 = id & 15;
            int gr = row0 + r; if (gr >= NN) gr = NN - 1;
            float4 v = *(const float4*)&x[(size_t)gr * INC + kt * 64 + c4 * 4];
            *(float4*)&xs[r][c4 * 4] = v;
        }
        // load W tile: 64 k x 128 cols (2048 float4)
#pragma unroll
        for (int i = 0; i < 8; i++) {
            int id = t + i * 256;
            int r  = id >> 5;        // 32 float4 per row
            int c4 = id & 31;
            float4 v = *(const float4*)&W[(size_t)(kt * 64 + r) * HC + c4 * 4];
            *(float4*)&ws[r][c4 * 4] = v;
        }
        __syncthreads();

#pragma unroll 8
        for (int kk = 0; kk < 64; kk++) {
            float4 b = *(float4*)&ws[kk][tx * 4];
#pragma unroll
            for (int r8 = 0; r8 < 8; r8++) {
                float a = xs[ty + r8 * 8][kk];   // warp-broadcast
                acc[r8].x += a * b.x;
                acc[r8].y += a * b.y;
                acc[r8].z += a * b.z;
                acc[r8].w += a * b.w;
            }
        }
        __syncthreads();
    }
#pragma unroll
    for (int r8 = 0; r8 < 8; r8++) {
        int r = row0 + ty + r8 * 8;
        if (r < NN) *(float4*)&g_h[(size_t)r * HC + tx * 4] = acc[r8];
    }
}

// ---------------- K2: per-node attention halves ------------------------------
__global__ void k_att(const float* __restrict__ att_src, const float* __restrict__ att_dst) {
    int nh = blockIdx.x * blockDim.x + threadIdx.x;
    if (nh >= NN * HH) return;
    int n  = nh >> 2;
    int hd = nh & 3;
    const float4* hv = (const float4*)&g_h[(size_t)n * HC + hd * CC];
    const float4* as = (const float4*)&att_src[hd * CC];
    const float4* ad = (const float4*)&att_dst[hd * CC];
    float s = 0.f, d = 0.f;
#pragma unroll
    for (int i = 0; i < 8; i++) {
        float4 h4 = hv[i], a4 = as[i], b4 = ad[i];
        s += h4.x * a4.x + h4.y * a4.y + h4.z * a4.z + h4.w * a4.w;
        d += h4.x * b4.x + h4.y * b4.y + h4.z * b4.z + h4.w * b4.w;
    }
    g_asrc[nh] = s;
    g_adst[nh] = d;
}

// ---------------- K0: init scratch -------------------------------------------
__global__ void k_init() {
    int i = blockIdx.x * blockDim.x + threadIdx.x;
    if (i < NN * HC) g_agg[i] = 0.f;
    if (i < NN * HH) { g_emax[i] = -INFINITY; g_den[i] = 0.f; }
}

// ---------------- K3: edge list (int32 [2,E] -> int2, append self loops) -----
__global__ void k_edges(const int* __restrict__ ei) {
    int i = blockIdx.x * blockDim.x + threadIdx.x;
    if (i >= ET) return;
    int s, d;
    if (i < EE) {
        s = ei[i];
        d = ei[EE + i];
        // defensive clamp: never let a bad index escape
        s = (s < 0) ? 0 : (s >= NN ? NN - 1 : s);
        d = (d < 0) ? 0 : (d >= NN ? NN - 1 : d);
    } else {
        s = d = i - EE;
    }
    g_edge[i] = make_int2(s, d);
}

// ---------------- K4: segment max of logits ----------------------------------
__global__ void k_max() {
    int i = blockIdx.x * blockDim.x + threadIdx.x;
    if (i >= ET) return;
    int2 e = g_edge[i];
    float4 as = *(const float4*)&g_asrc[(size_t)e.x * 4];
    float4 ad = *(const float4*)&g_adst[(size_t)e.y * 4];
    atomicMaxF(&g_emax[(size_t)e.y * 4 + 0], leaky(as.x + ad.x));
    atomicMaxF(&g_emax[(size_t)e.y * 4 + 1], leaky(as.y + ad.y));
    atomicMaxF(&g_emax[(size_t)e.y * 4 + 2], leaky(as.z + ad.z));
    atomicMaxF(&g_emax[(size_t)e.y * 4 + 3], leaky(as.w + ad.w));
}

// ---------------- K5: exp + denom --------------------------------------------
__global__ void k_exp() {
    int i = blockIdx.x * blockDim.x + threadIdx.x;
    if (i >= ET) return;
    int2 e = g_edge[i];
    float4 as = *(const float4*)&g_asrc[(size_t)e.x * 4];
    float4 ad = *(const float4*)&g_adst[(size_t)e.y * 4];
    float4 m  = *(const float4*)&g_emax[(size_t)e.y * 4];
    float4 ex;
    ex.x = expf(leaky(as.x + ad.x) - m.x);
    ex.y = expf(leaky(as.y + ad.y) - m.y);
    ex.z = expf(leaky(as.z + ad.z) - m.z);
    ex.w = expf(leaky(as.w + ad.w) - m.w);
    *(float4*)&g_ex[(size_t)i * 4] = ex;
    atomicAdd(&g_den[(size_t)e.y * 4 + 0], ex.x);
    atomicAdd(&g_den[(size_t)e.y * 4 + 1], ex.y);
    atomicAdd(&g_den[(size_t)e.y * 4 + 2], ex.z);
    atomicAdd(&g_den[(size_t)e.y * 4 + 3], ex.w);
}

// ---------------- K6: weighted scatter-sum (warp per edge) -------------------
__global__ void k_agg() {
    int w = (int)((blockIdx.x * (size_t)blockDim.x + threadIdx.x) >> 5);
    if (w >= ET) return;
    int lane = threadIdx.x & 31;
    int2 e = g_edge[w];
    int hd = lane >> 3;                         // head = (lane*4)/32
    float alpha = g_ex[(size_t)w * 4 + hd] / g_den[(size_t)e.y * 4 + hd];
    float4 hv = *(const float4*)&g_h[(size_t)e.x * HC + lane * 4];
    float* dst = &g_agg[(size_t)e.y * HC + lane * 4];
    atomicAdd(dst + 0, alpha * hv.x);
    atomicAdd(dst + 1, alpha * hv.y);
    atomicAdd(dst + 2, alpha * hv.z);
    atomicAdd(dst + 3, alpha * hv.w);
}

// ---------------- K7: out = elu(agg + bias) @ lin_W + lin_b ------------------
__global__ void k_out(const float* __restrict__ bias, const float* __restrict__ lin_W,
                      const float* __restrict__ lin_b, float* __restrict__ out) {
    __shared__ float ws[HC * OUTC];   // 32 KB
    __shared__ float bs[HC];
    __shared__ float lb[OUTC];
    int t = threadIdx.x;
    for (int i = t; i < HC * OUTC / 4; i += 256)
        ((float4*)ws)[i] = ((const float4*)lin_W)[i];
    if (t < HC)   bs[t] = bias[t];
    if (t < OUTC) lb[t] = lin_b[t];
    __syncthreads();

    int warp = t >> 5, lane = t & 31;
    for (int r = blockIdx.x * 8 + warp; r < NN; r += gridDim.x * 8) {
        float acc0 = 0.f, acc1 = 0.f;
#pragma unroll
        for (int kb = 0; kb < 4; kb++) {
            int k = kb * 32 + lane;
            float v = g_agg[(size_t)r * HC + k] + bs[k];
            v = v > 0.f ? v : expm1f(v);        // ELU(alpha=1)
#pragma unroll
            for (int j = 0; j < 32; j++) {
                float a = __shfl_sync(0xffffffffu, v, j);
                int kk = kb * 32 + j;
                acc0 += a * ws[kk * OUTC + lane];
                acc1 += a * ws[kk * OUTC + 32 + lane];
            }
        }
        out[(size_t)r * OUTC + lane]      = acc0 + lb[lane];
        out[(size_t)r * OUTC + 32 + lane] = acc1 + lb[lane + 32];
    }
}

// ---------------- launch ------------------------------------------------------
extern "C" void kernel_launch(void* const* d_in, const int* in_sizes, int n_in,
                              void* d_out, int out_size) {
    const float* x       = (const float*)d_in[0];
    const int*   eidx    = (const int*)d_in[1];     // int32 [2, E]
    const float* W       = (const float*)d_in[2];
    const float* att_src = (const float*)d_in[3];
    const float* att_dst = (const float*)d_in[4];
    const float* bias    = (const float*)d_in[5];
    const float* lin_W   = (const float*)d_in[6];
    const float* lin_b   = (const float*)d_in[7];
    float*       out     = (float*)d_out;

    k_gemm1<<<(NN + 63) / 64, 256>>>(x, W);
    k_init <<<(NN * HC + 255) / 256, 256>>>();
    k_edges<<<(ET + 255) / 256, 256>>>(eidx);
    k_att  <<<(NN * HH + 255) / 256, 256>>>(att_src, att_dst);
    k_max  <<<(ET + 255) / 256, 256>>>();
    k_exp  <<<(ET + 255) / 256, 256>>>();
    {
        size_t threads = (size_t)ET * 32;
        k_agg<<<(unsigned)((threads + 255) / 256), 256>>>();
    }
    k_out<<<625, 256>>>(bias, lin_W, lin_b, out);
}

// round 4
// speedup vs baseline: 2.3941x; 2.3941x over previous
#include <cuda_runtime.h>
#include <math.h>

#define NN   50000
#define EE   1600000
#define ET   (EE + NN)     // edges incl. self loops = 1,650,000
#define INC  256
#define HC   128           // H*C
#define HH   4
#define CC   32
#define OUTC 64
#define SCAN_BLKS ((NN + 255) / 256)   // 196

// ---------------- scratch (device globals; no allocation allowed) -------------
__device__ __align__(16) float g_h[(size_t)NN * HC];        // 25.6 MB
__device__ __align__(16) float g_asrc[(size_t)NN * HH];
__device__ __align__(16) float g_adst[(size_t)NN * HH];
__device__ __align__(16) float g_agg[(size_t)NN * HC];      // 25.6 MB
__device__            int   g_deg[NN];
__device__            int   g_off[NN + 1];
__device__            int   g_cur[NN];
__device__            int   g_bsum[SCAN_BLKS];
__device__            int   g_csr[ET];                       // 6.6 MB

// ---------------- helpers ----------------------------------------------------
__device__ __forceinline__ float leaky(float v) {
    return v >= 0.0f ? v : 0.2f * v;
}
__device__ __forceinline__ int clampN(int v) {
    return v < 0 ? 0 : (v >= NN ? NN - 1 : v);
}

// ---------------- K1: h = x @ W  (64x128 tile per block) ---------------------
__global__ void k_gemm1(const float* __restrict__ x, const float* __restrict__ W) {
    __shared__ float xs[64][64];
    __shared__ float ws[64][128];
    const int t  = threadIdx.x;
    const int tx = t & 31;
    const int ty = t >> 5;
    const int row0 = blockIdx.x * 64;

    float4 acc[8];
#pragma unroll
    for (int i = 0; i < 8; i++) acc[i] = make_float4(0.f, 0.f, 0.f, 0.f);

    for (int kt = 0; kt < 4; kt++) {
#pragma unroll
        for (int i = 0; i < 4; i++) {
            int id = t + i * 256;
            int r  = id >> 4;
            int c4 = id & 15;
            int gr = row0 + r; if (gr >= NN) gr = NN - 1;
            *(float4*)&xs[r][c4 * 4] =
                *(const float4*)&x[(size_t)gr * INC + kt * 64 + c4 * 4];
        }
#pragma unroll
        for (int i = 0; i < 8; i++) {
            int id = t + i * 256;
            int r  = id >> 5;
            int c4 = id & 31;
            *(float4*)&ws[r][c4 * 4] =
                *(const float4*)&W[(size_t)(kt * 64 + r) * HC + c4 * 4];
        }
        __syncthreads();

#pragma unroll 8
        for (int kk = 0; kk < 64; kk++) {
            float4 b = *(float4*)&ws[kk][tx * 4];
#pragma unroll
            for (int r8 = 0; r8 < 8; r8++) {
                float a = xs[ty + r8 * 8][kk];
                acc[r8].x += a * b.x;
                acc[r8].y += a * b.y;
                acc[r8].z += a * b.z;
                acc[r8].w += a * b.w;
            }
        }
        __syncthreads();
    }
#pragma unroll
    for (int r8 = 0; r8 < 8; r8++) {
        int r = row0 + ty + r8 * 8;
        if (r < NN) *(float4*)&g_h[(size_t)r * HC + tx * 4] = acc[r8];
    }
}

// ---------------- K2: per-node attention halves ------------------------------
__global__ void k_att(const float* __restrict__ att_src, const float* __restrict__ att_dst) {
    int nh = blockIdx.x * blockDim.x + threadIdx.x;
    if (nh >= NN * HH) return;
    int n  = nh >> 2;
    int hd = nh & 3;
    const float4* hv = (const float4*)&g_h[(size_t)n * HC + hd * CC];
    const float4* as = (const float4*)&att_src[hd * CC];
    const float4* ad = (const float4*)&att_dst[hd * CC];
    float s = 0.f, d = 0.f;
#pragma unroll
    for (int i = 0; i < 8; i++) {
        float4 h4 = hv[i], a4 = as[i], b4 = ad[i];
        s += h4.x * a4.x + h4.y * a4.y + h4.z * a4.z + h4.w * a4.w;
        d += h4.x * b4.x + h4.y * b4.y + h4.z * b4.z + h4.w * b4.w;
    }
    g_asrc[nh] = s;
    g_adst[nh] = d;
}

// ---------------- CSR build ---------------------------------------------------
// deg init to 1 (self loop)
__global__ void k_initdeg() {
    int i = blockIdx.x * blockDim.x + threadIdx.x;
    if (i < NN) g_deg[i] = 1;
}

// histogram of destinations
__global__ void k_hist(const int* __restrict__ ei) {
    int i = blockIdx.x * blockDim.x + threadIdx.x;
    if (i >= EE) return;
    atomicAdd(&g_deg[clampN(ei[EE + i])], 1);
}

// per-block exclusive scan of deg -> g_off (block-local), block sums -> g_bsum
__global__ void k_scanA() {
    __shared__ int sh[256];
    int t = threadIdx.x;
    int idx = blockIdx.x * 256 + t;
    int v = (idx < NN) ? g_deg[idx] : 0;
    sh[t] = v;
    __syncthreads();
#pragma unroll
    for (int o = 1; o < 256; o <<= 1) {
        int u = (t >= o) ? sh[t - o] : 0;
        __syncthreads();
        sh[t] += u;
        __syncthreads();
    }
    if (idx < NN) g_off[idx] = sh[t] - v;   // exclusive within block
    if (t == 255) g_bsum[blockIdx.x] = sh[255];
}

// exclusive scan of block sums (single block)
__global__ void k_scanB() {
    __shared__ int sh[SCAN_BLKS];
    int t = threadIdx.x;
    int v = (t < SCAN_BLKS) ? g_bsum[t] : 0;
    if (t < SCAN_BLKS) sh[t] = v;
    __syncthreads();
    for (int o = 1; o < SCAN_BLKS; o <<= 1) {
        int u = (t >= o && t < SCAN_BLKS) ? sh[t - o] : 0;
        __syncthreads();
        if (t < SCAN_BLKS) sh[t] += u;
        __syncthreads();
    }
    if (t < SCAN_BLKS) g_bsum[t] = sh[t] - v;
}

// finalize offsets, write self-loop at segment head, init cursor
__global__ void k_prep() {
    int n = blockIdx.x * blockDim.x + threadIdx.x;
    if (n >= NN) return;
    int off = g_off[n] + g_bsum[n >> 8];
    g_off[n] = off;
    g_csr[off] = n;          // self loop first
    g_cur[n] = off + 1;
    if (n == 0) g_off[NN] = ET;
}

// scatter edges into CSR by destination
__global__ void k_scatter(const int* __restrict__ ei) {
    int i = blockIdx.x * blockDim.x + threadIdx.x;
    if (i >= EE) return;
    int s = clampN(ei[i]);
    int d = clampN(ei[EE + i]);
    int pos = atomicAdd(&g_cur[d], 1);
    g_csr[pos] = s;
}

// ---------------- K6: fused softmax + aggregation (warp per dst) --------------
__global__ void k_aggr() {
    int w = (int)((blockIdx.x * (size_t)blockDim.x + threadIdx.x) >> 5);
    if (w >= NN) return;
    int lane = threadIdx.x & 31;
    int hd = lane >> 3;                     // head owning this lane's 4 channels

    int beg = g_off[w];
    int end = g_off[w + 1];
    float adh = g_adst[(size_t)w * 4 + hd];

    float4 acc = make_float4(0.f, 0.f, 0.f, 0.f);
    float den = 0.f;

    for (int p = beg; p < end; p += 32) {
        int cnt = end - p; if (cnt > 32) cnt = 32;
        int src = (lane < cnt) ? g_csr[p + lane] : 0;
#pragma unroll 4
        for (int j = 0; j < cnt; j++) {
            int s = __shfl_sync(0xffffffffu, src, j);
            float e  = leaky(g_asrc[(size_t)s * 4 + hd] + adh);
            float ex = __expf(e);
            float4 hv = *(const float4*)&g_h[(size_t)s * HC + lane * 4];
            acc.x += ex * hv.x;
            acc.y += ex * hv.y;
            acc.z += ex * hv.z;
            acc.w += ex * hv.w;
            den += ex;
        }
    }
    float inv = 1.0f / den;
    acc.x *= inv; acc.y *= inv; acc.z *= inv; acc.w *= inv;
    *(float4*)&g_agg[(size_t)w * HC + lane * 4] = acc;
}

// ---------------- K7: out = elu(agg + bias) @ lin_W + lin_b ------------------
__global__ void k_out(const float* __restrict__ bias, const float* __restrict__ lin_W,
                      const float* __restrict__ lin_b, float* __restrict__ out) {
    __shared__ float ws[HC * OUTC];
    __shared__ float bs[HC];
    __shared__ float lb[OUTC];
    int t = threadIdx.x;
    for (int i = t; i < HC * OUTC / 4; i += 256)
        ((float4*)ws)[i] = ((const float4*)lin_W)[i];
    if (t < HC)   bs[t] = bias[t];
    if (t < OUTC) lb[t] = lin_b[t];
    __syncthreads();

    int warp = t >> 5, lane = t & 31;
    for (int r = blockIdx.x * 8 + warp; r < NN; r += gridDim.x * 8) {
        float acc0 = 0.f, acc1 = 0.f;
#pragma unroll
        for (int kb = 0; kb < 4; kb++) {
            int k = kb * 32 + lane;
            float v = g_agg[(size_t)r * HC + k] + bs[k];
            v = v > 0.f ? v : expm1f(v);
#pragma unroll
            for (int j = 0; j < 32; j++) {
                float a = __shfl_sync(0xffffffffu, v, j);
                int kk = kb * 32 + j;
                acc0 += a * ws[kk * OUTC + lane];
                acc1 += a * ws[kk * OUTC + 32 + lane];
            }
        }
        out[(size_t)r * OUTC + lane]      = acc0 + lb[lane];
        out[(size_t)r * OUTC + 32 + lane] = acc1 + lb[lane + 32];
    }
}

// ---------------- launch ------------------------------------------------------
extern "C" void kernel_launch(void* const* d_in, const int* in_sizes, int n_in,
                              void* d_out, int out_size) {
    const float* x       = (const float*)d_in[0];
    const int*   eidx    = (const int*)d_in[1];     // int32 [2, E]
    const float* W       = (const float*)d_in[2];
    const float* att_src = (const float*)d_in[3];
    const float* att_dst = (const float*)d_in[4];
    const float* bias    = (const float*)d_in[5];
    const float* lin_W   = (const float*)d_in[6];
    const float* lin_b   = (const float*)d_in[7];
    float*       out     = (float*)d_out;

    k_gemm1  <<<(NN + 63) / 64, 256>>>(x, W);
    k_att    <<<(NN * HH + 255) / 256, 256>>>(att_src, att_dst);
    k_initdeg<<<(NN + 255) / 256, 256>>>();
    k_hist   <<<(EE + 255) / 256, 256>>>(eidx);
    k_scanA  <<<SCAN_BLKS, 256>>>();
    k_scanB  <<<1, 256>>>();
    k_prep   <<<(NN + 255) / 256, 256>>>();
    k_scatter<<<(EE + 255) / 256, 256>>>(eidx);
    k_aggr   <<<(NN * 32 + 255) / 256, 256>>>();
    k_out    <<<625, 256>>>(bias, lin_W, lin_b, out);
}

// round 5
// speedup vs baseline: 2.6185x; 1.0937x over previous
#include <cuda_runtime.h>
#include <cuda_fp16.h>
#include <math.h>

#define NN   50000
#define EE   1600000
#define ET   (EE + NN)     // edges incl. self loops = 1,650,000
#define INC  256
#define HC   128           // H*C
#define HH   4
#define CC   32
#define OUTC 64
#define SCAN_BLKS ((NN + 255) / 256)   // 196

// ---------------- scratch (device globals; no allocation allowed) -------------
__device__ __align__(16) __half g_hh[(size_t)NN * HC];      // 12.8 MB fp16 h
__device__ __align__(16) float g_asrc[(size_t)NN * HH];
__device__ __align__(16) float g_adst[(size_t)NN * HH];
__device__ __align__(16) float g_agg[(size_t)NN * HC];      // 25.6 MB
__device__            int   g_deg[NN];
__device__            int   g_off[NN + 1];
__device__            int   g_cur[NN];
__device__            int   g_bsum[SCAN_BLKS];
__device__            int   g_csr[ET];                       // 6.6 MB

// ---------------- helpers ----------------------------------------------------
__device__ __forceinline__ float leaky(float v) {
    return v >= 0.0f ? v : 0.2f * v;
}
__device__ __forceinline__ int clampN(int v) {
    return v < 0 ? 0 : (v >= NN ? NN - 1 : v);
}
__device__ __forceinline__ float dot4(float4 a, float4 b) {
    return a.x * b.x + a.y * b.y + a.z * b.z + a.w * b.w;
}

// ---------------- K1: h = x @ W (128x128 tile, 8x8/thread) + fused attention --
// Writes g_hh (fp16) and g_asrc/g_adst (fp32) directly.
__global__ void __launch_bounds__(256) k_gemm1(
        const float* __restrict__ x, const float* __restrict__ W,
        const float* __restrict__ att_src, const float* __restrict__ att_dst) {
    __shared__ float xs[16][132];   // [k][row], transposed, padded
    __shared__ float ws[16][128];   // [k][col]
    const int t  = threadIdx.x;
    const int cx = t & 15;          // col group
    const int ty = t >> 4;          // row group
    const int row0 = blockIdx.x * 128;

    // attention vectors for this thread's 8 columns
    float4 attS[2], attD[2];
    attS[0] = *(const float4*)&att_src[cx * 4];
    attS[1] = *(const float4*)&att_src[64 + cx * 4];
    attD[0] = *(const float4*)&att_dst[cx * 4];
    attD[1] = *(const float4*)&att_dst[64 + cx * 4];

    float4 acc[2][2][4];            // [rowblk][colblk][rowelem] x 4 cols
#pragma unroll
    for (int i = 0; i < 2; i++)
#pragma unroll
        for (int j = 0; j < 2; j++)
#pragma unroll
            for (int r = 0; r < 4; r++)
                acc[i][j][r] = make_float4(0.f, 0.f, 0.f, 0.f);

    for (int kt = 0; kt < 16; kt++) {
        // x tile: 128 rows x 16 k, transposed store
#pragma unroll
        for (int u = 0; u < 2; u++) {
            int id = t + u * 256;
            int r  = id >> 2;
            int kq = id & 3;
            int gr = row0 + r; if (gr >= NN) gr = NN - 1;
            float4 v = *(const float4*)&x[(size_t)gr * INC + kt * 16 + kq * 4];
            xs[kq * 4 + 0][r] = v.x;
            xs[kq * 4 + 1][r] = v.y;
            xs[kq * 4 + 2][r] = v.z;
            xs[kq * 4 + 3][r] = v.w;
        }
        // W tile: 16 k x 128 cols
#pragma unroll
        for (int u = 0; u < 2; u++) {
            int id = t + u * 256;
            int k  = id >> 5;
            int c4 = id & 31;
            *(float4*)&ws[k][c4 * 4] =
                *(const float4*)&W[(size_t)(kt * 16 + k) * HC + c4 * 4];
        }
        __syncthreads();

#pragma unroll
        for (int k = 0; k < 16; k++) {
            float4 a0 = *(float4*)&xs[k][ty * 4];
            float4 a1 = *(float4*)&xs[k][64 + ty * 4];
            float4 b0 = *(float4*)&ws[k][cx * 4];
            float4 b1 = *(float4*)&ws[k][64 + cx * 4];
            float ar0[4] = {a0.x, a0.y, a0.z, a0.w};
            float ar1[4] = {a1.x, a1.y, a1.z, a1.w};
#pragma unroll
            for (int r = 0; r < 4; r++) {
                acc[0][0][r].x += ar0[r] * b0.x; acc[0][0][r].y += ar0[r] * b0.y;
                acc[0][0][r].z += ar0[r] * b0.z; acc[0][0][r].w += ar0[r] * b0.w;
                acc[0][1][r].x += ar0[r] * b1.x; acc[0][1][r].y += ar0[r] * b1.y;
                acc[0][1][r].z += ar0[r] * b1.z; acc[0][1][r].w += ar0[r] * b1.w;
                acc[1][0][r].x += ar1[r] * b0.x; acc[1][0][r].y += ar1[r] * b0.y;
                acc[1][0][r].z += ar1[r] * b0.z; acc[1][0][r].w += ar1[r] * b0.w;
                acc[1][1][r].x += ar1[r] * b1.x; acc[1][1][r].y += ar1[r] * b1.y;
                acc[1][1][r].z += ar1[r] * b1.z; acc[1][1][r].w += ar1[r] * b1.w;
            }
        }
        __syncthreads();
    }

    // Epilogue: fp16 h store + fused attention halves
    const unsigned FULL = 0xffffffffu;
#pragma unroll
    for (int i = 0; i < 2; i++) {
#pragma unroll
        for (int r = 0; r < 4; r++) {
            int row = row0 + i * 64 + ty * 4 + r;
            float s0 = dot4(acc[i][0][r], attS[0]);
            float s1 = dot4(acc[i][1][r], attS[1]);
            float d0 = dot4(acc[i][0][r], attD[0]);
            float d1 = dot4(acc[i][1][r], attD[1]);
#pragma unroll
            for (int o = 1; o < 8; o <<= 1) {
                s0 += __shfl_xor_sync(FULL, s0, o);
                s1 += __shfl_xor_sync(FULL, s1, o);
                d0 += __shfl_xor_sync(FULL, d0, o);
                d1 += __shfl_xor_sync(FULL, d1, o);
            }
            if (row < NN) {
                if ((cx & 7) == 0) {
                    int hA = cx >> 3;    // 0 or 1
                    g_asrc[(size_t)row * 4 + hA]     = s0;
                    g_asrc[(size_t)row * 4 + 2 + hA] = s1;
                    g_adst[(size_t)row * 4 + hA]     = d0;
                    g_adst[(size_t)row * 4 + 2 + hA] = d1;
                }
                __half2 p0 = __floats2half2_rn(acc[i][0][r].x, acc[i][0][r].y);
                __half2 p1 = __floats2half2_rn(acc[i][0][r].z, acc[i][0][r].w);
                __half2 q0 = __floats2half2_rn(acc[i][1][r].x, acc[i][1][r].y);
                __half2 q1 = __floats2half2_rn(acc[i][1][r].z, acc[i][1][r].w);
                uint2 pv, qv;
                pv.x = *(unsigned*)&p0; pv.y = *(unsigned*)&p1;
                qv.x = *(unsigned*)&q0; qv.y = *(unsigned*)&q1;
                *(uint2*)&g_hh[(size_t)row * HC + cx * 4]      = pv;
                *(uint2*)&g_hh[(size_t)row * HC + 64 + cx * 4] = qv;
            }
        }
    }
}

// ---------------- CSR build ---------------------------------------------------
__global__ void k_initdeg() {
    int i = blockIdx.x * blockDim.x + threadIdx.x;
    if (i < NN) g_deg[i] = 1;
}

__global__ void k_hist(const int* __restrict__ ei) {
    int i = blockIdx.x * blockDim.x + threadIdx.x;
    if (i >= EE) return;
    atomicAdd(&g_deg[clampN(ei[EE + i])], 1);
}

__global__ void k_scanA() {
    __shared__ int sh[256];
    int t = threadIdx.x;
    int idx = blockIdx.x * 256 + t;
    int v = (idx < NN) ? g_deg[idx] : 0;
    sh[t] = v;
    __syncthreads();
#pragma unroll
    for (int o = 1; o < 256; o <<= 1) {
        int u = (t >= o) ? sh[t - o] : 0;
        __syncthreads();
        sh[t] += u;
        __syncthreads();
    }
    if (idx < NN) g_off[idx] = sh[t] - v;
    if (t == 255) g_bsum[blockIdx.x] = sh[255];
}

__global__ void k_scanB() {
    __shared__ int sh[SCAN_BLKS];
    int t = threadIdx.x;
    int v = (t < SCAN_BLKS) ? g_bsum[t] : 0;
    if (t < SCAN_BLKS) sh[t] = v;
    __syncthreads();
    for (int o = 1; o < SCAN_BLKS; o <<= 1) {
        int u = (t >= o && t < SCAN_BLKS) ? sh[t - o] : 0;
        __syncthreads();
        if (t < SCAN_BLKS) sh[t] += u;
        __syncthreads();
    }
    if (t < SCAN_BLKS) g_bsum[t] = sh[t] - v;
}

__global__ void k_prep() {
    int n = blockIdx.x * blockDim.x + threadIdx.x;
    if (n >= NN) return;
    int off = g_off[n] + g_bsum[n >> 8];
    g_off[n] = off;
    g_csr[off] = n;          // self loop first
    g_cur[n] = off + 1;
    if (n == 0) g_off[NN] = ET;
}

__global__ void k_scatter(const int* __restrict__ ei) {
    int i = blockIdx.x * blockDim.x + threadIdx.x;
    if (i >= EE) return;
    int s = clampN(ei[i]);
    int d = clampN(ei[EE + i]);
    int pos = atomicAdd(&g_cur[d], 1);
    g_csr[pos] = s;
}

// ---------------- K6: fused softmax + aggregation (warp per dst, fp16 gather) --
__global__ void k_aggr() {
    int w = (int)((blockIdx.x * (size_t)blockDim.x + threadIdx.x) >> 5);
    if (w >= NN) return;
    int lane = threadIdx.x & 31;
    int hd = lane >> 3;

    int beg = g_off[w];
    int end = g_off[w + 1];
    float adh = g_adst[(size_t)w * 4 + hd];

    float4 acc = make_float4(0.f, 0.f, 0.f, 0.f);
    float den = 0.f;

    for (int p = beg; p < end; p += 32) {
        int cnt = end - p; if (cnt > 32) cnt = 32;
        int src = (lane < cnt) ? g_csr[p + lane] : 0;
#pragma unroll 4
        for (int j = 0; j < cnt; j++) {
            int s = __shfl_sync(0xffffffffu, src, j);
            float e  = leaky(g_asrc[(size_t)s * 4 + hd] + adh);
            float ex = __expf(e);
            uint2 hv = *(const uint2*)&g_hh[(size_t)s * HC + lane * 4];
            float2 f0 = __half22float2(*(__half2*)&hv.x);
            float2 f1 = __half22float2(*(__half2*)&hv.y);
            acc.x += ex * f0.x;
            acc.y += ex * f0.y;
            acc.z += ex * f1.x;
            acc.w += ex * f1.y;
            den += ex;
        }
    }
    float inv = 1.0f / den;
    acc.x *= inv; acc.y *= inv; acc.z *= inv; acc.w *= inv;
    *(float4*)&g_agg[(size_t)w * HC + lane * 4] = acc;
}

// ---------------- K7: out = elu(agg + bias) @ lin_W + lin_b ------------------
__global__ void k_out(const float* __restrict__ bias, const float* __restrict__ lin_W,
                      const float* __restrict__ lin_b, float* __restrict__ out) {
    __shared__ float ws[HC * OUTC];
    __shared__ float bs[HC];
    __shared__ float lb[OUTC];
    int t = threadIdx.x;
    for (int i = t; i < HC * OUTC / 4; i += 256)
        ((float4*)ws)[i] = ((const float4*)lin_W)[i];
    if (t < HC)   bs[t] = bias[t];
    if (t < OUTC) lb[t] = lin_b[t];
    __syncthreads();

    int warp = t >> 5, lane = t & 31;
    for (int r = blockIdx.x * 8 + warp; r < NN; r += gridDim.x * 8) {
        float acc0 = 0.f, acc1 = 0.f;
#pragma unroll
        for (int kb = 0; kb < 4; kb++) {
            int k = kb * 32 + lane;
            float v = g_agg[(size_t)r * HC + k] + bs[k];
            v = v > 0.f ? v : expm1f(v);
#pragma unroll
            for (int j = 0; j < 32; j++) {
                float a = __shfl_sync(0xffffffffu, v, j);
                int kk = kb * 32 + j;
                acc0 += a * ws[kk * OUTC + lane];
                acc1 += a * ws[kk * OUTC + 32 + lane];
            }
        }
        out[(size_t)r * OUTC + lane]      = acc0 + lb[lane];
        out[(size_t)r * OUTC + 32 + lane] = acc1 + lb[lane + 32];
    }
}

// ---------------- launch ------------------------------------------------------
extern "C" void kernel_launch(void* const* d_in, const int* in_sizes, int n_in,
                              void* d_out, int out_size) {
    const float* x       = (const float*)d_in[0];
    const int*   eidx    = (const int*)d_in[1];     // int32 [2, E]
    const float* W       = (const float*)d_in[2];
    const float* att_src = (const float*)d_in[3];
    const float* att_dst = (const float*)d_in[4];
    const float* bias    = (const float*)d_in[5];
    const float* lin_W   = (const float*)d_in[6];
    const float* lin_b   = (const float*)d_in[7];
    float*       out     = (float*)d_out;

    k_gemm1  <<<(NN + 127) / 128, 256>>>(x, W, att_src, att_dst);
    k_initdeg<<<(NN + 255) / 256, 256>>>();
    k_hist   <<<(EE + 255) / 256, 256>>>(eidx);
    k_scanA  <<<SCAN_BLKS, 256>>>();
    k_scanB  <<<1, 256>>>();
    k_prep   <<<(NN + 255) / 256, 256>>>();
    k_scatter<<<(EE + 255) / 256, 256>>>(eidx);
    k_aggr   <<<(NN * 32 + 255) / 256, 256>>>();
    k_out    <<<625, 256>>>(bias, lin_W, lin_b, out);
}